// round 7
// baseline (speedup 1.0000x reference)
#include <cuda_runtime.h>
#include <cuda_fp16.h>
#include <math.h>

#define DET0 128
#define DET1 128
#define VOL_ELEMS (128*128*128)
#define N_STEPS 226
#define N_RAYS (4*128*128)
#define WARPS_PER_BLOCK 8

// per-ray state: [0]=(s0,s1,s2,tmin) [1]=(d0,d1,d2,tmax)
__device__ float4 g_ray[N_RAYS * 2];
// per-ray interior chunk range: jA | (jB<<8)
__device__ int g_jr[N_RAYS];

// y-pair packed fp16 volume: P(b,x,y,z) = half2( v(x,y,z), v(x,y+1,z) )
__device__ unsigned g_P[4 * VOL_ELEMS];

// ---------------- setup: per-ray geometry + interior range ----------------
__global__ void __launch_bounds__(256) drr_setup_kernel(
    const float* __restrict__ params)   // (4,6)
{
    const int ray = blockIdx.x * 256 + threadIdx.x;
    const int iv = ray & 127;
    const int iu = (ray >> 7) & 127;
    const int b  = ray >> 14;

    const float* p = params + b * 6;
    float sx = sinf(p[0]), cx = cosf(p[0]);
    float sy = sinf(p[1]), cy = cosf(p[1]);
    float sz = sinf(p[2]), cz = cosf(p[2]);

    float T00 = cy*cz,  T01 = cx*sz + sx*sy*cz,  T02 = sx*sz - cx*sy*cz;
    float T10 = -cy*sz, T11 = cx*cz - sx*sy*sz,  T12 = sx*cz + cx*sy*sz;
    float T20 = sy,     T21 = -sx*cy,            T22 = cx*cy;

    float tv0 = -p[3], tv1 = -p[4], tv2 = 1000.0f - p[5];
    float s0 = 64.0f - (T00*tv0 + T01*tv1 + T02*tv2);
    float s1 = 64.0f - (T10*tv0 + T11*tv1 + T12*tv2);
    float s2 = 64.0f - (T20*tv0 + T21*tv1 + T22*tv2);

    float qx = ((float)iu + 0.5f) * 0.001f - 0.064f;
    float qy = ((float)iv + 0.5f) * 0.001f - 0.064f;

    float d0 = T00*qx + T01*qy + T02;
    float d1 = T10*qx + T11*qy + T12;
    float d2 = T20*qx + T21*qy + T22;
    float nrm = sqrtf(d0*d0 + d1*d1 + d2*d2);
    d0 /= nrm; d1 /= nrm; d2 /= nrm;

    float sd0 = (fabsf(d0) < 1e-8f) ? 1e-8f : d0;
    float sd1 = (fabsf(d1) < 1e-8f) ? 1e-8f : d1;
    float sd2 = (fabsf(d2) < 1e-8f) ? 1e-8f : d2;
    float a0 = (0.0f - s0) / sd0, b0_ = (128.0f - s0) / sd0;
    float a1 = (0.0f - s1) / sd1, b1_ = (128.0f - s1) / sd1;
    float a2 = (0.0f - s2) / sd2, b2_ = (128.0f - s2) / sd2;
    float tmin = fmaxf(fmaxf(fminf(a0,b0_), fminf(a1,b1_)), fminf(a2,b2_));
    tmin = fmaxf(tmin, 0.0f);
    float tmax = fminf(fminf(fmaxf(a0,b0_), fmaxf(a1,b1_)), fmaxf(a2,b2_));

    float e0 = (0.5f - s0) / sd0, g0 = (126.5f - s0) / sd0;
    float e1 = (0.5f - s1) / sd1, g1 = (126.5f - s1) / sd1;
    float e2 = (0.5f - s2) / sd2, g2 = (126.5f - s2) / sd2;
    float t_in  = fmaxf(fmaxf(fminf(e0,g0), fminf(e1,g1)), fminf(e2,g2));
    float t_out = fminf(fminf(fmaxf(e0,g0), fmaxf(e1,g1)), fmaxf(e2,g2));

    // interior chunk range [jA, jB): same float predicate the march used
    int jA = 8, jB = 8;
    #pragma unroll
    for (int j = 0; j < 8; j++) {
        float kbase = (float)(j * 32);
        float tk0 = tmin + (kbase + 0.5f);
        float u   = tmin + (kbase + 31.5f);
        bool fast = (tk0 >= t_in) && (u <= t_out) && (u < tmax) && (j < 7);
        if (fast && jA == 8) jA = j;
        if (!fast && jA != 8 && jB == 8) jB = j;
    }
    if (jA == 8) { jA = 0; jB = 0; }

    g_ray[ray*2 + 0] = make_float4(s0, s1, s2, tmin);
    g_ray[ray*2 + 1] = make_float4(d0, d1, d2, tmax);
    g_jr[ray] = jA | (jB << 8);
}

// ---------------- prepass: build y-pair packed fp16 volume ----------------
// thread handles 8 consecutive z at fixed (b, x, y)
__global__ void __launch_bounds__(256) drr_pack_kernel(
    const float* __restrict__ vol)
{
    const int tid = blockIdx.x * 256 + threadIdx.x;   // 4*128*128*16 threads
    const int zb = tid & 15;
    const int y  = (tid >> 4) & 127;
    const int x  = (tid >> 11) & 127;
    const int b  = tid >> 18;

    const size_t row = (((size_t)(b * 128 + x)) * 128 + y) * 128;
    const float* r1 = vol + ((y < 127) ? row + 128 : row);   // clamp; P(y=127) unused by fast path
    const int z0 = zb * 8;

    float4 a0 = __ldg((const float4*)(vol + row + z0));
    float4 a1 = __ldg((const float4*)(vol + row + z0 + 4));
    float4 c0 = __ldg((const float4*)(r1 + z0));
    float4 c1 = __ldg((const float4*)(r1 + z0 + 4));

    __half2 h0 = __floats2half2_rn(a0.x, c0.x);
    __half2 h1 = __floats2half2_rn(a0.y, c0.y);
    __half2 h2 = __floats2half2_rn(a0.z, c0.z);
    __half2 h3 = __floats2half2_rn(a0.w, c0.w);
    __half2 h4 = __floats2half2_rn(a1.x, c1.x);
    __half2 h5 = __floats2half2_rn(a1.y, c1.y);
    __half2 h6 = __floats2half2_rn(a1.z, c1.z);
    __half2 h7 = __floats2half2_rn(a1.w, c1.w);

    uint4 o0, o1;
    o0.x = *reinterpret_cast<unsigned*>(&h0);
    o0.y = *reinterpret_cast<unsigned*>(&h1);
    o0.z = *reinterpret_cast<unsigned*>(&h2);
    o0.w = *reinterpret_cast<unsigned*>(&h3);
    o1.x = *reinterpret_cast<unsigned*>(&h4);
    o1.y = *reinterpret_cast<unsigned*>(&h5);
    o1.z = *reinterpret_cast<unsigned*>(&h6);
    o1.w = *reinterpret_cast<unsigned*>(&h7);

    *reinterpret_cast<uint4*>(&g_P[row + z0])     = o0;
    *reinterpret_cast<uint4*>(&g_P[row + z0 + 4]) = o1;
}

// ---------------- interior march: fast path only, max occupancy ----------------
__device__ __forceinline__ float interior_sample(
    const unsigned* __restrict__ P,
    float tk, float d0, float d1, float d2,
    float s0, float s1, float s2)
{
    float px = fmaf(tk, d0, s0);
    float py = fmaf(tk, d1, s1);
    float pz = fmaf(tk, d2, s2);
    float fx = floorf(px), fy = floorf(py), fz = floorf(pz);
    float rx = px - fx, ry = py - fy, rz = pz - fz;

    float Wf = fmaf(fx, 16384.0f, fmaf(fy, 128.0f, fz));
    int r = (int)Wf;
    unsigned u00 = __ldg(P + r);
    unsigned u01 = __ldg(P + r + 1);
    unsigned u10 = __ldg(P + r + 16384);
    unsigned u11 = __ldg(P + r + 16385);

    float2 f00 = __half22float2(*reinterpret_cast<__half2*>(&u00));
    float2 f01 = __half22float2(*reinterpret_cast<__half2*>(&u01));
    float2 f10 = __half22float2(*reinterpret_cast<__half2*>(&u10));
    float2 f11 = __half22float2(*reinterpret_cast<__half2*>(&u11));

    float z0a = fmaf(rz, f01.x - f00.x, f00.x);
    float z0b = fmaf(rz, f01.y - f00.y, f00.y);
    float z1a = fmaf(rz, f11.x - f10.x, f10.x);
    float z1b = fmaf(rz, f11.y - f10.y, f10.y);
    float ly0 = fmaf(ry, z0b - z0a, z0a);
    float ly1 = fmaf(ry, z1b - z1a, z1a);
    return fmaf(rx, ly1 - ly0, ly0);
}

__global__ void __launch_bounds__(WARPS_PER_BLOCK * 32, 8) drr_interior_kernel(
    float* __restrict__ out)
{
    const int lane    = threadIdx.x & 31;
    const int warp_id = threadIdx.x >> 5;
    const int ray     = blockIdx.x * WARPS_PER_BLOCK + warp_id;
    const int b       = ray >> 14;

    const float4 A = __ldg(&g_ray[ray*2 + 0]);
    const float4 B = __ldg(&g_ray[ray*2 + 1]);
    const float s0 = A.x, s1 = A.y, s2 = A.z, tmin = A.w;
    const float d0 = B.x, d1 = B.y, d2 = B.z;
    const int jr = g_jr[ray];
    const int jA = jr & 0xFF, jB = (jr >> 8) & 0xFF;

    const unsigned* __restrict__ P = g_P + (size_t)b * VOL_ELEMS;
    const float lane_f = (float)lane + 0.5f;

    float acc = 0.0f;
    int j = jA;
    // pairs: 8 loads in flight
    for (; j + 1 < jB; j += 2) {
        float tka = tmin + ((float)(j * 32)       + lane_f);
        float tkb = tmin + ((float)(j * 32 + 32)  + lane_f);
        float sa = interior_sample(P, tka, d0, d1, d2, s0, s1, s2);
        float sb = interior_sample(P, tkb, d0, d1, d2, s0, s1, s2);
        acc += sa + sb;
    }
    if (j < jB) {
        float tk = tmin + ((float)(j * 32) + lane_f);
        acc += interior_sample(P, tk, d0, d1, d2, s0, s1, s2);
    }

    #pragma unroll
    for (int off = 16; off > 0; off >>= 1)
        acc += __shfl_xor_sync(0xFFFFFFFFu, acc, off);

    if (lane == 0)
        out[ray] = acc * 0.1f;
}

// ---------------- edges: guarded exact fp32 path for boundary chunks ----------------
__global__ void __launch_bounds__(WARPS_PER_BLOCK * 32) drr_edges_kernel(
    const float* __restrict__ vol,
    float* __restrict__ out)
{
    const int lane    = threadIdx.x & 31;
    const int warp_id = threadIdx.x >> 5;
    const int ray     = blockIdx.x * WARPS_PER_BLOCK + warp_id;
    const int b       = ray >> 14;

    const float4 A = __ldg(&g_ray[ray*2 + 0]);
    const float4 B = __ldg(&g_ray[ray*2 + 1]);
    const float s0 = A.x, s1 = A.y, s2 = A.z, tmin = A.w;
    const float d0 = B.x, d1 = B.y, d2 = B.z, tmax = B.w;
    const int jr = g_jr[ray];
    const int jA = jr & 0xFF, jB = (jr >> 8) & 0xFF;

    const float* __restrict__ v = vol + (size_t)b * VOL_ELEMS;
    const float lane_f = (float)lane + 0.5f;

    float acc = 0.0f;
    for (int j = 0; j < 8; j++) {
        if (j >= jA && j < jB) continue;      // interior handled elsewhere
        float kbase = (float)(j * 32);
        float tk0 = tmin + (kbase + 0.5f);
        if (tk0 >= tmax) break;               // warp-uniform

        float tk = tmin + (kbase + lane_f);
        int k = j * 32 + lane;
        bool live = (k < N_STEPS) && (tk < tmax);

        float px = fmaf(tk, d0, s0);
        float py = fmaf(tk, d1, s1);
        float pz = fmaf(tk, d2, s2);
        float fx = floorf(px), fy = floorf(py), fz = floorf(pz);
        int ix = (int)fx, iy = (int)fy, iz = (int)fz;
        float rx = px - fx, ry = py - fy, rz = pz - fz;

        float wx0 = ((unsigned)ix       < 128u) ? (1.0f - rx) : 0.0f;
        float wx1 = ((unsigned)(ix + 1) < 128u) ? rx          : 0.0f;
        float wy0 = ((unsigned)iy       < 128u) ? (1.0f - ry) : 0.0f;
        float wy1 = ((unsigned)(iy + 1) < 128u) ? ry          : 0.0f;
        float wz0 = ((unsigned)iz       < 128u) ? (1.0f - rz) : 0.0f;
        float wz1 = ((unsigned)(iz + 1) < 128u) ? rz          : 0.0f;
        if (!live) { wz0 = 0.0f; wz1 = 0.0f; }

        int cx0 = min(max(ix,     0), 127);
        int cx1 = min(max(ix + 1, 0), 127);
        int cy0 = min(max(iy,     0), 127);
        int cy1 = min(max(iy + 1, 0), 127);
        int cz0 = min(max(iz,     0), 127);
        int cz1 = min(max(iz + 1, 0), 127);

        int r00 = cx0 * 16384 + cy0 * 128;
        int r01 = cx0 * 16384 + cy1 * 128;
        int r10 = cx1 * 16384 + cy0 * 128;
        int r11 = cx1 * 16384 + cy1 * 128;

        float v000 = __ldg(v + r00 + cz0);
        float v001 = __ldg(v + r00 + cz1);
        float v010 = __ldg(v + r01 + cz0);
        float v011 = __ldg(v + r01 + cz1);
        float v100 = __ldg(v + r10 + cz0);
        float v101 = __ldg(v + r10 + cz1);
        float v110 = __ldg(v + r11 + cz0);
        float v111 = __ldg(v + r11 + cz1);

        float w00 = wx0 * wy0;
        float w01 = wx0 * wy1;
        float w10 = wx1 * wy0;
        float w11 = wx1 * wy1;

        float sz0v = v000 * w00;
        sz0v = fmaf(v010, w01, sz0v);
        sz0v = fmaf(v100, w10, sz0v);
        sz0v = fmaf(v110, w11, sz0v);
        float sz1v = v001 * w00;
        sz1v = fmaf(v011, w01, sz1v);
        sz1v = fmaf(v101, w10, sz1v);
        sz1v = fmaf(v111, w11, sz1v);

        acc = fmaf(sz0v, wz0, acc);
        acc = fmaf(sz1v, wz1, acc);
    }

    #pragma unroll
    for (int off = 16; off > 0; off >>= 1)
        acc += __shfl_xor_sync(0xFFFFFFFFu, acc, off);

    if (lane == 0)
        out[ray] += acc * 0.1f;
}

extern "C" void kernel_launch(void* const* d_in, const int* in_sizes, int n_in,
                              void* d_out, int out_size)
{
    const float* vol    = (const float*)d_in[0];
    const float* params = (const float*)d_in[1];
    float* out = (float*)d_out;

    drr_pack_kernel<<<(4 * 128 * 128 * 16) / 256, 256>>>(vol);
    drr_setup_kernel<<<N_RAYS / 256, 256>>>(params);
    drr_interior_kernel<<<N_RAYS / WARPS_PER_BLOCK, WARPS_PER_BLOCK * 32>>>(out);
    drr_edges_kernel<<<N_RAYS / WARPS_PER_BLOCK, WARPS_PER_BLOCK * 32>>>(vol, out);
}

// round 8
// speedup vs baseline: 1.2384x; 1.2384x over previous
#include <cuda_runtime.h>
#include <cuda_fp16.h>
#include <math.h>

#define VOL_ELEMS (128*128*128)
#define N_RAYS (4*128*128)
#define WARPS_PER_BLOCK 8

// padded packed volume dims: P2(b, xp, yp, zp) = half2( vpad(x,y,z), vpad(x,y+1,z) )
// xp = x+1 (x in [-1,129]), yp = y+1 (y in [-1,128]), zp = z+4 (z in [-4,131])
#define PZ 136                 // z slots (4 low pad for 16B alignment, 4 high)
#define PY 130                 // y slots
#define PX 131                 // x slots
#define SX (PY*PZ)             // 17680
#define PBATCH (PX*SX)         // 2316080
// r = ix*SX + iy*PZ + iz + ROFF  with ROFF = SX + PZ + 4
#define ROFF 17820

__device__ float4   g_ray[N_RAYS * 2];
__device__ unsigned g_P2[4 * PBATCH];      // 37 MB

// ---------------- setup: per-ray geometry ----------------
__global__ void __launch_bounds__(256) drr_setup_kernel(
    const float* __restrict__ params)   // (4,6)
{
    const int ray = blockIdx.x * 256 + threadIdx.x;
    const int iv = ray & 127;
    const int iu = (ray >> 7) & 127;
    const int b  = ray >> 14;

    const float* p = params + b * 6;
    float sx = sinf(p[0]), cx = cosf(p[0]);
    float sy = sinf(p[1]), cy = cosf(p[1]);
    float sz = sinf(p[2]), cz = cosf(p[2]);

    float T00 = cy*cz,  T01 = cx*sz + sx*sy*cz,  T02 = sx*sz - cx*sy*cz;
    float T10 = -cy*sz, T11 = cx*cz - sx*sy*sz,  T12 = sx*cz + cx*sy*sz;
    float T20 = sy,     T21 = -sx*cy,            T22 = cx*cy;

    float tv0 = -p[3], tv1 = -p[4], tv2 = 1000.0f - p[5];
    float s0 = 64.0f - (T00*tv0 + T01*tv1 + T02*tv2);
    float s1 = 64.0f - (T10*tv0 + T11*tv1 + T12*tv2);
    float s2 = 64.0f - (T20*tv0 + T21*tv1 + T22*tv2);

    float qx = ((float)iu + 0.5f) * 0.001f - 0.064f;
    float qy = ((float)iv + 0.5f) * 0.001f - 0.064f;

    float d0 = T00*qx + T01*qy + T02;
    float d1 = T10*qx + T11*qy + T12;
    float d2 = T20*qx + T21*qy + T22;
    float nrm = sqrtf(d0*d0 + d1*d1 + d2*d2);
    d0 /= nrm; d1 /= nrm; d2 /= nrm;

    float sd0 = (fabsf(d0) < 1e-8f) ? 1e-8f : d0;
    float sd1 = (fabsf(d1) < 1e-8f) ? 1e-8f : d1;
    float sd2 = (fabsf(d2) < 1e-8f) ? 1e-8f : d2;
    float a0 = (0.0f - s0) / sd0, b0_ = (128.0f - s0) / sd0;
    float a1 = (0.0f - s1) / sd1, b1_ = (128.0f - s1) / sd1;
    float a2 = (0.0f - s2) / sd2, b2_ = (128.0f - s2) / sd2;
    float tmin = fmaxf(fmaxf(fminf(a0,b0_), fminf(a1,b1_)), fminf(a2,b2_));
    tmin = fmaxf(tmin, 0.0f);
    float tmax = fminf(fminf(fmaxf(a0,b0_), fmaxf(a1,b1_)), fmaxf(a2,b2_));

    g_ray[ray*2 + 0] = make_float4(s0, s1, s2, tmin);
    g_ray[ray*2 + 1] = make_float4(d0, d1, d2, tmax);
}

// ---------------- pack: interior rows (yp in [1,128]) ----------------
__global__ void __launch_bounds__(256) drr_pack_kernel(
    const float* __restrict__ vol)
{
    const int tid = blockIdx.x * 256 + threadIdx.x;   // 4*128*128*16
    const int zb = tid & 15;
    const int y  = (tid >> 4) & 127;
    const int x  = (tid >> 11) & 127;
    const int b  = tid >> 18;

    const size_t row = (((size_t)(b * 128 + x)) * 128 + y) * 128;
    const int z0 = zb * 8;

    float4 a0 = __ldg((const float4*)(vol + row + z0));
    float4 a1 = __ldg((const float4*)(vol + row + z0 + 4));
    float4 c0 = make_float4(0.f,0.f,0.f,0.f), c1 = c0;
    if (y < 127) {
        c0 = __ldg((const float4*)(vol + row + 128 + z0));
        c1 = __ldg((const float4*)(vol + row + 128 + z0 + 4));
    }

    __half2 h0 = __floats2half2_rn(a0.x, c0.x);
    __half2 h1 = __floats2half2_rn(a0.y, c0.y);
    __half2 h2 = __floats2half2_rn(a0.z, c0.z);
    __half2 h3 = __floats2half2_rn(a0.w, c0.w);
    __half2 h4 = __floats2half2_rn(a1.x, c1.x);
    __half2 h5 = __floats2half2_rn(a1.y, c1.y);
    __half2 h6 = __floats2half2_rn(a1.z, c1.z);
    __half2 h7 = __floats2half2_rn(a1.w, c1.w);

    uint4 o0, o1;
    o0.x = *reinterpret_cast<unsigned*>(&h0);
    o0.y = *reinterpret_cast<unsigned*>(&h1);
    o0.z = *reinterpret_cast<unsigned*>(&h2);
    o0.w = *reinterpret_cast<unsigned*>(&h3);
    o1.x = *reinterpret_cast<unsigned*>(&h4);
    o1.y = *reinterpret_cast<unsigned*>(&h5);
    o1.z = *reinterpret_cast<unsigned*>(&h6);
    o1.w = *reinterpret_cast<unsigned*>(&h7);

    size_t w = (size_t)b * PBATCH + (size_t)(x + 1) * SX + (size_t)(y + 1) * PZ + (z0 + 4);
    *reinterpret_cast<uint4*>(&g_P2[w])     = o0;
    *reinterpret_cast<uint4*>(&g_P2[w + 4]) = o1;
}

// ---------------- pack: yp = 0 plane (y = -1): pair = (0, v(x,0,z)) ----------------
__global__ void __launch_bounds__(256) drr_pack_y0_kernel(
    const float* __restrict__ vol)
{
    const int tid = blockIdx.x * 256 + threadIdx.x;   // 4*128*16
    const int zb = tid & 15;
    const int x  = (tid >> 4) & 127;
    const int b  = tid >> 11;

    const size_t row = ((size_t)(b * 128 + x)) * 128 * 128;   // y = 0 row
    const int z0 = zb * 8;

    float4 a0 = __ldg((const float4*)(vol + row + z0));
    float4 a1 = __ldg((const float4*)(vol + row + z0 + 4));

    __half2 h0 = __floats2half2_rn(0.f, a0.x);
    __half2 h1 = __floats2half2_rn(0.f, a0.y);
    __half2 h2 = __floats2half2_rn(0.f, a0.z);
    __half2 h3 = __floats2half2_rn(0.f, a0.w);
    __half2 h4 = __floats2half2_rn(0.f, a1.x);
    __half2 h5 = __floats2half2_rn(0.f, a1.y);
    __half2 h6 = __floats2half2_rn(0.f, a1.z);
    __half2 h7 = __floats2half2_rn(0.f, a1.w);

    uint4 o0, o1;
    o0.x = *reinterpret_cast<unsigned*>(&h0);
    o0.y = *reinterpret_cast<unsigned*>(&h1);
    o0.z = *reinterpret_cast<unsigned*>(&h2);
    o0.w = *reinterpret_cast<unsigned*>(&h3);
    o1.x = *reinterpret_cast<unsigned*>(&h4);
    o1.y = *reinterpret_cast<unsigned*>(&h5);
    o1.z = *reinterpret_cast<unsigned*>(&h6);
    o1.w = *reinterpret_cast<unsigned*>(&h7);

    size_t w = (size_t)b * PBATCH + (size_t)(x + 1) * SX + (z0 + 4);
    *reinterpret_cast<uint4*>(&g_P2[w])     = o0;
    *reinterpret_cast<uint4*>(&g_P2[w + 4]) = o1;
}

// ---------------- pack: zero borders ----------------
__global__ void __launch_bounds__(256) drr_border_kernel()
{
    const int t = blockIdx.x * 256 + threadIdx.x;     // 4*131*130
    if (t >= 4 * PX * PY) return;
    const int yp = t % PY;
    const int r2 = t / PY;
    const int xp = r2 % PX;
    const int b  = r2 / PX;

    size_t base = (size_t)b * PBATCH + (size_t)xp * SX + (size_t)yp * PZ;
    uint4 z4 = make_uint4(0u, 0u, 0u, 0u);

    if (xp == 0 || xp == 129 || xp == 130 || yp == 129) {
        #pragma unroll
        for (int i = 0; i < PZ / 4; i++)
            *reinterpret_cast<uint4*>(&g_P2[base + i * 4]) = z4;
    } else {
        *reinterpret_cast<uint4*>(&g_P2[base])       = z4;   // z pads -4..-1
        *reinterpret_cast<uint4*>(&g_P2[base + 132]) = z4;   // z pads 128..131
    }
}

// ---------------- march: single uniform fast path ----------------
__device__ __forceinline__ float drr_sample(
    const unsigned* __restrict__ P,
    float tk, float tmax,
    float d0, float d1, float d2,
    float s0, float s1, float s2)
{
    float px = fmaf(tk, d0, s0);
    float py = fmaf(tk, d1, s1);
    float pz = fmaf(tk, d2, s2);
    // clamp (no-op for live lanes; keeps dead lanes in the padded index range)
    px = fminf(fmaxf(px, -0.5f), 128.5f);
    py = fminf(fmaxf(py, -0.5f), 128.5f);
    pz = fminf(fmaxf(pz, -0.5f), 128.5f);
    float fx = floorf(px), fy = floorf(py), fz = floorf(pz);
    float rx = px - fx, ry = py - fy, rz = pz - fz;

    // exact integer-valued float index (max ~2.3M < 2^24)
    int r = (int)fmaf(fx, (float)SX, fmaf(fy, (float)PZ, fz + (float)ROFF));

    unsigned u00 = __ldg(P + r);
    unsigned u01 = __ldg(P + r + 1);
    unsigned u10 = __ldg(P + r + SX);
    unsigned u11 = __ldg(P + r + SX + 1);

    float2 f00 = __half22float2(*reinterpret_cast<__half2*>(&u00));
    float2 f01 = __half22float2(*reinterpret_cast<__half2*>(&u01));
    float2 f10 = __half22float2(*reinterpret_cast<__half2*>(&u10));
    float2 f11 = __half22float2(*reinterpret_cast<__half2*>(&u11));

    float z0a = fmaf(rz, f01.x - f00.x, f00.x);
    float z0b = fmaf(rz, f01.y - f00.y, f00.y);
    float z1a = fmaf(rz, f11.x - f10.x, f10.x);
    float z1b = fmaf(rz, f11.y - f10.y, f10.y);
    float ly0 = fmaf(ry, z0b - z0a, z0a);
    float ly1 = fmaf(ry, z1b - z1a, z1a);
    float s = fmaf(rx, ly1 - ly0, ly0);
    return (tk < tmax) ? s : 0.0f;   // mask: k<226 is implied (tmax-tmin <= 221.7)
}

__global__ void __launch_bounds__(WARPS_PER_BLOCK * 32, 8) drr_march_kernel(
    float* __restrict__ out)
{
    const int lane    = threadIdx.x & 31;
    const int warp_id = threadIdx.x >> 5;
    const int ray     = blockIdx.x * WARPS_PER_BLOCK + warp_id;
    const int b       = ray >> 14;

    const float4 A = __ldg(&g_ray[ray*2 + 0]);
    const float4 B = __ldg(&g_ray[ray*2 + 1]);
    const float s0 = A.x, s1 = A.y, s2 = A.z, tmin = A.w;
    const float d0 = B.x, d1 = B.y, d2 = B.z, tmax = B.w;

    const unsigned* __restrict__ P = g_P2 + (size_t)b * PBATCH;
    const float lane_f = (float)lane + 0.5f;

    // number of chunks whose first step has tk0 < tmax
    int nc = __float2int_ru((tmax - tmin - 0.5f) * 0.03125f);
    nc = max(0, min(nc, 8));

    float acc = 0.0f;
    int j = 0;
    for (; j + 1 < nc; j += 2) {
        float tka = tmin + ((float)(j * 32)      + lane_f);
        float tkb = tmin + ((float)(j * 32 + 32) + lane_f);
        float sa = drr_sample(P, tka, tmax, d0, d1, d2, s0, s1, s2);
        float sb = drr_sample(P, tkb, tmax, d0, d1, d2, s0, s1, s2);
        acc += sa + sb;
    }
    if (j < nc) {
        float tk = tmin + ((float)(j * 32) + lane_f);
        acc += drr_sample(P, tk, tmax, d0, d1, d2, s0, s1, s2);
    }

    #pragma unroll
    for (int off = 16; off > 0; off >>= 1)
        acc += __shfl_xor_sync(0xFFFFFFFFu, acc, off);

    if (lane == 0)
        out[ray] = acc * 0.1f;
}

extern "C" void kernel_launch(void* const* d_in, const int* in_sizes, int n_in,
                              void* d_out, int out_size)
{
    const float* vol    = (const float*)d_in[0];
    const float* params = (const float*)d_in[1];
    float* out = (float*)d_out;

    drr_border_kernel<<<(4 * PX * PY + 255) / 256, 256>>>();
    drr_pack_y0_kernel<<<(4 * 128 * 16) / 256, 256>>>(vol);
    drr_pack_kernel<<<(4 * 128 * 128 * 16) / 256, 256>>>(vol);
    drr_setup_kernel<<<N_RAYS / 256, 256>>>(params);
    drr_march_kernel<<<N_RAYS / WARPS_PER_BLOCK, WARPS_PER_BLOCK * 32>>>(out);
}

// round 9
// speedup vs baseline: 1.3497x; 1.0899x over previous
#include <cuda_runtime.h>
#include <cuda_fp16.h>
#include <math.h>

#define VOL_ELEMS (128*128*128)
#define N_RAYS (4*128*128)
#define WARPS_PER_BLOCK 8

// padded packed volume: P2(b, xp, yp, zp) = half2( vpad(x,y,z), vpad(x,y+1,z) )
// xp = x+1 (x in [-1,129]), yp = y+1 (y in [-1,128]), zp = z+4 (z in [-4,131])
#define PZ 136
#define PY 130
#define PX 131
#define SX (PY*PZ)             // 17680
#define PBATCH (PX*SX)         // 2316080
#define ROFF (SX + PZ + 4)     // 17820

__device__ float4   g_ray[N_RAYS * 2];
__device__ unsigned g_P2[4 * PBATCH];      // 37 MB

// ---------------- setup: per-ray geometry ----------------
__global__ void __launch_bounds__(128) drr_setup_kernel(
    const float* __restrict__ params)   // (4,6)
{
    const int ray = blockIdx.x * 128 + threadIdx.x;
    const int iv = ray & 127;
    const int iu = (ray >> 7) & 127;
    const int b  = ray >> 14;

    const float* p = params + b * 6;
    float sx, cx, sy, cy, sz, cz;
    __sincosf(p[0], &sx, &cx);
    __sincosf(p[1], &sy, &cy);
    __sincosf(p[2], &sz, &cz);

    float T00 = cy*cz,  T01 = cx*sz + sx*sy*cz,  T02 = sx*sz - cx*sy*cz;
    float T10 = -cy*sz, T11 = cx*cz - sx*sy*sz,  T12 = sx*cz + cx*sy*sz;
    float T20 = sy,     T21 = -sx*cy,            T22 = cx*cy;

    float tv0 = -p[3], tv1 = -p[4], tv2 = 1000.0f - p[5];
    float s0 = 64.0f - (T00*tv0 + T01*tv1 + T02*tv2);
    float s1 = 64.0f - (T10*tv0 + T11*tv1 + T12*tv2);
    float s2 = 64.0f - (T20*tv0 + T21*tv1 + T22*tv2);

    float qx = ((float)iu + 0.5f) * 0.001f - 0.064f;
    float qy = ((float)iv + 0.5f) * 0.001f - 0.064f;

    float d0 = T00*qx + T01*qy + T02;
    float d1 = T10*qx + T11*qy + T12;
    float d2 = T20*qx + T21*qy + T22;
    float nrm = sqrtf(d0*d0 + d1*d1 + d2*d2);
    d0 /= nrm; d1 /= nrm; d2 /= nrm;

    float sd0 = (fabsf(d0) < 1e-8f) ? 1e-8f : d0;
    float sd1 = (fabsf(d1) < 1e-8f) ? 1e-8f : d1;
    float sd2 = (fabsf(d2) < 1e-8f) ? 1e-8f : d2;
    float a0 = (0.0f - s0) / sd0, b0_ = (128.0f - s0) / sd0;
    float a1 = (0.0f - s1) / sd1, b1_ = (128.0f - s1) / sd1;
    float a2 = (0.0f - s2) / sd2, b2_ = (128.0f - s2) / sd2;
    float tmin = fmaxf(fmaxf(fminf(a0,b0_), fminf(a1,b1_)), fminf(a2,b2_));
    tmin = fmaxf(tmin, 0.0f);
    float tmax = fminf(fminf(fmaxf(a0,b0_), fmaxf(a1,b1_)), fmaxf(a2,b2_));

    g_ray[ray*2 + 0] = make_float4(s0, s1, s2, tmin);
    g_ray[ray*2 + 1] = make_float4(d0, d1, d2, tmax);
}

// ---------------- pack: interior rows (yp in [1,128]) ----------------
__global__ void __launch_bounds__(256) drr_pack_kernel(
    const float* __restrict__ vol)
{
    const int tid = blockIdx.x * 256 + threadIdx.x;   // 4*128*128*16
    const int zb = tid & 15;
    const int y  = (tid >> 4) & 127;
    const int x  = (tid >> 11) & 127;
    const int b  = tid >> 18;

    const size_t row = (((size_t)(b * 128 + x)) * 128 + y) * 128;
    const int z0 = zb * 8;

    float4 a0 = __ldg((const float4*)(vol + row + z0));
    float4 a1 = __ldg((const float4*)(vol + row + z0 + 4));
    float4 c0 = make_float4(0.f,0.f,0.f,0.f), c1 = c0;
    if (y < 127) {
        c0 = __ldg((const float4*)(vol + row + 128 + z0));
        c1 = __ldg((const float4*)(vol + row + 128 + z0 + 4));
    }

    __half2 h0 = __floats2half2_rn(a0.x, c0.x);
    __half2 h1 = __floats2half2_rn(a0.y, c0.y);
    __half2 h2 = __floats2half2_rn(a0.z, c0.z);
    __half2 h3 = __floats2half2_rn(a0.w, c0.w);
    __half2 h4 = __floats2half2_rn(a1.x, c1.x);
    __half2 h5 = __floats2half2_rn(a1.y, c1.y);
    __half2 h6 = __floats2half2_rn(a1.z, c1.z);
    __half2 h7 = __floats2half2_rn(a1.w, c1.w);

    uint4 o0, o1;
    o0.x = *reinterpret_cast<unsigned*>(&h0);
    o0.y = *reinterpret_cast<unsigned*>(&h1);
    o0.z = *reinterpret_cast<unsigned*>(&h2);
    o0.w = *reinterpret_cast<unsigned*>(&h3);
    o1.x = *reinterpret_cast<unsigned*>(&h4);
    o1.y = *reinterpret_cast<unsigned*>(&h5);
    o1.z = *reinterpret_cast<unsigned*>(&h6);
    o1.w = *reinterpret_cast<unsigned*>(&h7);

    size_t w = (size_t)b * PBATCH + (size_t)(x + 1) * SX + (size_t)(y + 1) * PZ + (z0 + 4);
    *reinterpret_cast<uint4*>(&g_P2[w])     = o0;
    *reinterpret_cast<uint4*>(&g_P2[w + 4]) = o1;
}

// ---------------- pack: borders + y0 plane (fused) ----------------
#define NB_BORDER (4 * PX * PY)            // zero rows / z-pads
#define NB_Y0     (4 * 128 * 16)           // y = -1 plane threads
__global__ void __launch_bounds__(256) drr_border_kernel(
    const float* __restrict__ vol)
{
    const int t = blockIdx.x * 256 + threadIdx.x;
    if (t < NB_BORDER) {
        const int yp = t % PY;
        const int r2 = t / PY;
        const int xp = r2 % PX;
        const int b  = r2 / PX;

        size_t base = (size_t)b * PBATCH + (size_t)xp * SX + (size_t)yp * PZ;
        uint4 z4 = make_uint4(0u, 0u, 0u, 0u);

        if (xp == 0 || xp == 129 || xp == 130 || yp == 129) {
            #pragma unroll
            for (int i = 0; i < PZ / 4; i++)
                *reinterpret_cast<uint4*>(&g_P2[base + i * 4]) = z4;
        } else {
            *reinterpret_cast<uint4*>(&g_P2[base])       = z4;   // z pads -4..-1
            *reinterpret_cast<uint4*>(&g_P2[base + 132]) = z4;   // z pads 128..131
        }
        return;
    }
    const int t2 = t - NB_BORDER;
    if (t2 >= NB_Y0) return;
    // yp = 0 plane (y = -1): pair = (0, v(x,0,z))
    const int zb = t2 & 15;
    const int x  = (t2 >> 4) & 127;
    const int b  = t2 >> 11;

    const size_t row = ((size_t)(b * 128 + x)) * 128 * 128;   // y = 0 row
    const int z0 = zb * 8;

    float4 a0 = __ldg((const float4*)(vol + row + z0));
    float4 a1 = __ldg((const float4*)(vol + row + z0 + 4));

    __half2 h0 = __floats2half2_rn(0.f, a0.x);
    __half2 h1 = __floats2half2_rn(0.f, a0.y);
    __half2 h2 = __floats2half2_rn(0.f, a0.z);
    __half2 h3 = __floats2half2_rn(0.f, a0.w);
    __half2 h4 = __floats2half2_rn(0.f, a1.x);
    __half2 h5 = __floats2half2_rn(0.f, a1.y);
    __half2 h6 = __floats2half2_rn(0.f, a1.z);
    __half2 h7 = __floats2half2_rn(0.f, a1.w);

    uint4 o0, o1;
    o0.x = *reinterpret_cast<unsigned*>(&h0);
    o0.y = *reinterpret_cast<unsigned*>(&h1);
    o0.z = *reinterpret_cast<unsigned*>(&h2);
    o0.w = *reinterpret_cast<unsigned*>(&h3);
    o1.x = *reinterpret_cast<unsigned*>(&h4);
    o1.y = *reinterpret_cast<unsigned*>(&h5);
    o1.z = *reinterpret_cast<unsigned*>(&h6);
    o1.w = *reinterpret_cast<unsigned*>(&h7);

    size_t w = (size_t)b * PBATCH + (size_t)(x + 1) * SX + (z0 + 4);
    *reinterpret_cast<uint4*>(&g_P2[w])     = o0;
    *reinterpret_cast<uint4*>(&g_P2[w + 4]) = o1;
}

// ---------------- march ----------------
__device__ __forceinline__ float drr_sample(
    const unsigned* __restrict__ P,
    float tk, float tmax,
    float d0, float d1, float d2,
    float s0, float s1, float s2)
{
    // single clamp: dead lanes sample at the exit point (in padded range);
    // live lanes unchanged (bit-exact)
    float tc = fminf(tk, tmax);
    float px = fmaf(tc, d0, s0);
    float py = fmaf(tc, d1, s1);
    float pz = fmaf(tc, d2, s2);
    float fx = floorf(px), fy = floorf(py), fz = floorf(pz);
    float rx = px - fx, ry = py - fy, rz = pz - fz;

    int r = (int)fmaf(fx, (float)SX, fmaf(fy, (float)PZ, fz + (float)ROFF));

    unsigned u00 = __ldg(P + r);
    unsigned u01 = __ldg(P + r + 1);
    unsigned u10 = __ldg(P + r + SX);
    unsigned u11 = __ldg(P + r + SX + 1);

    float2 f00 = __half22float2(*reinterpret_cast<__half2*>(&u00));
    float2 f01 = __half22float2(*reinterpret_cast<__half2*>(&u01));
    float2 f10 = __half22float2(*reinterpret_cast<__half2*>(&u10));
    float2 f11 = __half22float2(*reinterpret_cast<__half2*>(&u11));

    float z0a = fmaf(rz, f01.x - f00.x, f00.x);
    float z0b = fmaf(rz, f01.y - f00.y, f00.y);
    float z1a = fmaf(rz, f11.x - f10.x, f10.x);
    float z1b = fmaf(rz, f11.y - f10.y, f10.y);
    float ly0 = fmaf(ry, z0b - z0a, z0a);
    float ly1 = fmaf(ry, z1b - z1a, z1a);
    float s = fmaf(rx, ly1 - ly0, ly0);
    return (tk < tmax) ? s : 0.0f;
}

__global__ void __launch_bounds__(WARPS_PER_BLOCK * 32, 8) drr_march_kernel(
    float* __restrict__ out)
{
    const int lane    = threadIdx.x & 31;
    const int warp_id = threadIdx.x >> 5;
    const int ray     = blockIdx.x * WARPS_PER_BLOCK + warp_id;
    const int b       = ray >> 14;

    const float4 A = __ldg(&g_ray[ray*2 + 0]);
    const float4 B = __ldg(&g_ray[ray*2 + 1]);
    const float s0 = A.x, s1 = A.y, s2 = A.z, tmin = A.w;
    const float d0 = B.x, d1 = B.y, d2 = B.z, tmax = B.w;

    const unsigned* __restrict__ P = g_P2 + (size_t)b * PBATCH;

    int nc = __float2int_ru((tmax - tmin - 0.5f) * 0.03125f);
    nc = max(0, min(nc, 8));

    const float t0 = tmin + ((float)lane + 0.5f);

    float acc = 0.0f;
    int j = 0;
    for (; j + 1 < nc; j += 2) {
        float tka = t0 + (float)(j * 32);
        float tkb = t0 + (float)(j * 32 + 32);
        float sa = drr_sample(P, tka, tmax, d0, d1, d2, s0, s1, s2);
        float sb = drr_sample(P, tkb, tmax, d0, d1, d2, s0, s1, s2);
        acc += sa + sb;
    }
    if (j < nc) {
        float tk = t0 + (float)(j * 32);
        acc += drr_sample(P, tk, tmax, d0, d1, d2, s0, s1, s2);
    }

    #pragma unroll
    for (int off = 16; off > 0; off >>= 1)
        acc += __shfl_xor_sync(0xFFFFFFFFu, acc, off);

    if (lane == 0)
        out[ray] = acc * 0.1f;
}

extern "C" void kernel_launch(void* const* d_in, const int* in_sizes, int n_in,
                              void* d_out, int out_size)
{
    const float* vol    = (const float*)d_in[0];
    const float* params = (const float*)d_in[1];
    float* out = (float*)d_out;

    drr_border_kernel<<<(NB_BORDER + NB_Y0 + 255) / 256, 256>>>(vol);
    drr_pack_kernel<<<(4 * 128 * 128 * 16) / 256, 256>>>(vol);
    drr_setup_kernel<<<N_RAYS / 128, 128>>>(params);
    drr_march_kernel<<<N_RAYS / WARPS_PER_BLOCK, WARPS_PER_BLOCK * 32>>>(out);
}